// round 7
// baseline (speedup 1.0000x reference)
#include <cuda_runtime.h>

// Psi11t flow force: F = 2*t*c0 * ( s x (Fs*b + Fbs) )
//   Fs = nbr4(s), b = s.Fs, Fbs = nbr4(s*b). Periodic 512x512, B=32, S=3.
// WARP-AUTONOMOUS register-marching stencil: each warp owns a 128-col y-segment
// (lane = one float4), marches XCHUNK x-rows. y-neighbor exchange via shuffles;
// segment-edge lanes (0,31) load s-halo scalars from gmem and recompute edge b
// locally. Zero shared memory, zero __syncthreads.

#define MASK 511
#define XCHUNK 16
#define FULL 0xFFFFFFFFu

__device__ __forceinline__ float4 operator+(float4 a, float4 b) {
    return make_float4(a.x + b.x, a.y + b.y, a.z + b.z, a.w + b.w);
}
__device__ __forceinline__ float4 fma4(float4 a, float4 b, float4 c) {
    return make_float4(fmaf(a.x, b.x, c.x), fmaf(a.y, b.y, c.y),
                       fmaf(a.z, b.z, c.z), fmaf(a.w, b.w, c.w));
}
__device__ __forceinline__ float4 crossm(float4 a, float4 b, float4 c, float4 d) {
    return make_float4(fmaf(a.x, b.x, -(c.x * d.x)), fmaf(a.y, b.y, -(c.y * d.y)),
                       fmaf(a.z, b.z, -(c.z * d.z)), fmaf(a.w, b.w, -(c.w * d.w)));
}
__device__ __forceinline__ float4 scale4(float k, float4 a) {
    return make_float4(k * a.x, k * a.y, k * a.z, k * a.w);
}
// y-1 shift across the warp: lane gets prev lane's .w; lane0 uses edge scalar.
__device__ __forceinline__ float4 ymx(float4 a, float edge, int lane) {
    float p = __shfl_up_sync(FULL, a.w, 1);
    if (lane == 0) p = edge;
    return make_float4(p, a.x, a.y, a.z);
}
// y+1 shift: lane gets next lane's .x; lane31 uses edge scalar.
__device__ __forceinline__ float4 ypx(float4 a, float edge, int lane) {
    float n = __shfl_down_sync(FULL, a.x, 1);
    if (lane == 31) n = edge;
    return make_float4(a.y, a.z, a.w, n);
}

__global__ __launch_bounds__(128, 5) void psi11t_kernel(
    const float* __restrict__ s,
    const float* __restrict__ tt,
    const float* __restrict__ c0,
    float* __restrict__ out)
{
    const int lane = threadIdx.x & 31;
    const int gw   = blockIdx.x * 4 + (threadIdx.x >> 5);   // 0..4095
    const int bb    = gw >> 7;          // 32 batches
    const int rem   = gw & 127;
    const int strip = rem >> 2;         // 32 strips of XCHUNK rows
    const int seg   = rem & 3;          // 4 y-segments of 128 cols
    const int x0 = strip * XCHUNK;
    const int Y0 = seg << 7;

    const long base = (long)bb * (3L << 18);
    const float* sb = s + base;
    const int yo = Y0 + 4 * lane;

    const float coeff = 2.0f * tt[0] * c0[0];

    const bool isEdge = (lane == 0) | (lane == 31);
    // halo y coords for edge lanes (periodic wrap across segment boundary)
    const int y1 = (lane == 0) ? ((Y0 - 1) & MASK) : ((Y0 + 128) & MASK);  // inner-1
    const int y2 = (lane == 0) ? ((Y0 - 2) & MASK) : ((Y0 + 129) & MASK);  // inner-2

    // Persistent state
    float4 sP[3], sC[3], sN[3];
    float4 bP, bC;
    float  e1C[3], e1N[3], e2N[3];   // halo s scalars (valid on lanes 0/31)
    float  bCh;                      // halo b scalar  (valid on lanes 0/31)

    // ---------------- Prologue ----------------
    {
        const int rA = (x0 - 2) & MASK, rP = (x0 - 1) & MASK;
        const int rC = x0, rN = x0 + 1;
        float4 sA[3];
        float e1P[3], e2C[3];
        #pragma unroll
        for (int c = 0; c < 3; ++c) {
            const float* cp = sb + ((long)c << 18);
            sA[c] = *(const float4*)(cp + ((long)rA << 9) + yo);
            sP[c] = *(const float4*)(cp + ((long)rP << 9) + yo);
            sC[c] = *(const float4*)(cp + ((long)rC << 9) + yo);
            sN[c] = *(const float4*)(cp + ((long)rN << 9) + yo);
        }
        if (isEdge) {
            #pragma unroll
            for (int c = 0; c < 3; ++c) {
                const float* cp = sb + ((long)c << 18);
                e1P[c] = cp[((long)rP << 9) + y1];
                e1C[c] = cp[((long)rC << 9) + y1];
                e1N[c] = cp[((long)rN << 9) + y1];
                e2C[c] = cp[((long)rC << 9) + y2];
                e2N[c] = cp[((long)rN << 9) + y2];
            }
        }

        // bP = sP . (sA + sC + ym(sP) + yp(sP))
        bP = make_float4(0.f, 0.f, 0.f, 0.f);
        #pragma unroll
        for (int c = 0; c < 3; ++c)
            bP = fma4(sP[c], sA[c] + sC[c] + ymx(sP[c], e1P[c], lane)
                                           + ypx(sP[c], e1P[c], lane), bP);

        // bC = sC . (sP + sN + ym(sC) + yp(sC))
        bC = make_float4(0.f, 0.f, 0.f, 0.f);
        #pragma unroll
        for (int c = 0; c < 3; ++c)
            bC = fma4(sC[c], sP[c] + sN[c] + ymx(sC[c], e1C[c], lane)
                                           + ypx(sC[c], e1C[c], lane), bC);

        // edge b at row x0: center=e1C, x-nbrs=e1P,e1N, y-nbrs=e2C + inner
        bCh = 0.f;
        #pragma unroll
        for (int c = 0; c < 3; ++c) {
            float inner = (lane == 0) ? sC[c].x : sC[c].w;
            bCh = fmaf(e1C[c], e1P[c] + e1N[c] + e2C[c] + inner, bCh);
        }
    }

    // ---------------- Main loop: rows x0 .. x0+XCHUNK-1 ----------------
    #pragma unroll 2
    for (int i = 0; i < XCHUNK; ++i) {
        const int x  = x0 + i;
        const int r2 = (x + 2) & MASK;

        // load row x+2
        float4 sN2[3];
        float e1N2[3], e2N2[3];
        #pragma unroll
        for (int c = 0; c < 3; ++c)
            sN2[c] = *(const float4*)(sb + ((long)c << 18) + ((long)r2 << 9) + yo);
        if (isEdge) {
            #pragma unroll
            for (int c = 0; c < 3; ++c) {
                const float* cp = sb + ((long)c << 18) + ((long)r2 << 9);
                e1N2[c] = cp[y1];
                e2N2[c] = cp[y2];
            }
        }

        // bN = sN . (sC + sN2 + ym(sN) + yp(sN))
        float4 bN = make_float4(0.f, 0.f, 0.f, 0.f);
        #pragma unroll
        for (int c = 0; c < 3; ++c)
            bN = fma4(sN[c], sC[c] + sN2[c] + ymx(sN[c], e1N[c], lane)
                                            + ypx(sN[c], e1N[c], lane), bN);

        // edge b at row x+1: center=e1N, x-nbrs=e1C,e1N2, y-nbrs=e2N + inner
        float bNh = 0.f;
        #pragma unroll
        for (int c = 0; c < 3; ++c) {
            float inner = (lane == 0) ? sN[c].x : sN[c].w;
            bNh = fmaf(e1N[c], e1C[c] + e1N2[c] + e2N[c] + inner, bNh);
        }

        // F at row x
        float byl = __shfl_up_sync(FULL, bC.w, 1);
        if (lane == 0) byl = bCh;
        float byr = __shfl_down_sync(FULL, bC.x, 1);
        if (lane == 31) byr = bCh;
        const float4 bym = make_float4(byl, bC.x, bC.y, bC.z);
        const float4 byp = make_float4(bC.y, bC.z, bC.w, byr);

        float4 Fv[3];
        #pragma unroll
        for (int c = 0; c < 3; ++c) {
            const float4 ymc = ymx(sC[c], e1C[c], lane);
            const float4 ypc = ypx(sC[c], e1C[c], lane);
            const float4 Fs  = sP[c] + sN[c] + ymc + ypc;
            const float4 Fbs = fma4(sP[c], bP,
                               fma4(sN[c], bN,
                               fma4(ymc, bym,
                                    make_float4(ypc.x * byp.x, ypc.y * byp.y,
                                                ypc.z * byp.z, ypc.w * byp.w))));
            Fv[c] = fma4(Fs, bC, Fbs);
        }

        const float4 F0 = crossm(sC[1], Fv[2], sC[2], Fv[1]);
        const float4 F1 = crossm(sC[2], Fv[0], sC[0], Fv[2]);
        const float4 F2 = crossm(sC[0], Fv[1], sC[1], Fv[0]);

        float* op = out + base + (((long)x) << 9) + yo;
        *(float4*)(op)              = scale4(coeff, F0);
        *(float4*)(op + (1L << 18)) = scale4(coeff, F1);
        *(float4*)(op + (2L << 18)) = scale4(coeff, F2);

        // rotate pipeline (pure register renames under unroll)
        #pragma unroll
        for (int c = 0; c < 3; ++c) {
            sP[c] = sC[c]; sC[c] = sN[c]; sN[c] = sN2[c];
            e1C[c] = e1N[c]; e1N[c] = e1N2[c]; e2N[c] = e2N2[c];
        }
        bP = bC; bC = bN; bCh = bNh;
    }
}

extern "C" void kernel_launch(void* const* d_in, const int* in_sizes, int n_in,
                              void* d_out, int out_size)
{
    const float* s  = (const float*)d_in[0];
    const float* t  = (const float*)d_in[1];
    const float* c0 = (const float*)d_in[2];
    float* out = (float*)d_out;

    // 32 batches * 32 strips * 4 segments = 4096 warps = 1024 blocks of 128
    psi11t_kernel<<<1024, 128>>>(s, t, c0, out);
}

// round 8
// speedup vs baseline: 1.4529x; 1.4529x over previous
#include <cuda_runtime.h>
#include <cstdint>

// Psi11t flow force: F = 2*t*c0 * ( s x (Fs*b + Fbs) )
//   Fs = nbr4(s), b = s.Fs, Fbs = nbr4(s*b). Periodic 512x512, B=32, S=3.
// Register-marching stencil + cp.async smem row-ring (4 slots, distance-2
// prefetch). 128 threads own the full Y=512 ring (float4/thread), march
// XCHUNK=16 x-rows. s-row boundary scalars read directly from the smem ring;
// only b boundary scalars use an STS/LDS exchange. Streaming stores.

#define MASK 511
#define XCHUNK 16
#define NTH 128

__device__ __forceinline__ float4 operator+(float4 a, float4 b) {
    return make_float4(a.x + b.x, a.y + b.y, a.z + b.z, a.w + b.w);
}
__device__ __forceinline__ float4 fma4(float4 a, float4 b, float4 c) {
    return make_float4(fmaf(a.x, b.x, c.x), fmaf(a.y, b.y, c.y),
                       fmaf(a.z, b.z, c.z), fmaf(a.w, b.w, c.w));
}
__device__ __forceinline__ float4 crossm(float4 a, float4 b, float4 c, float4 d) {
    return make_float4(fmaf(a.x, b.x, -(c.x * d.x)), fmaf(a.y, b.y, -(c.y * d.y)),
                       fmaf(a.z, b.z, -(c.z * d.z)), fmaf(a.w, b.w, -(c.w * d.w)));
}
__device__ __forceinline__ float4 ymv(float4 a, float lw) {
    return make_float4(lw, a.x, a.y, a.z);
}
__device__ __forceinline__ float4 ypv(float4 a, float rx) {
    return make_float4(a.y, a.z, a.w, rx);
}
__device__ __forceinline__ float4 scale4(float k, float4 a) {
    return make_float4(k * a.x, k * a.y, k * a.z, k * a.w);
}
__device__ __forceinline__ void cpa16(float* smem_dst, const float* g) {
    uint32_t sa = (uint32_t)__cvta_generic_to_shared(smem_dst);
    asm volatile("cp.async.cg.shared.global [%0], [%1], 16;" :: "r"(sa), "l"(g));
}
__device__ __forceinline__ void cpa_commit() {
    asm volatile("cp.async.commit_group;");
}
__device__ __forceinline__ void cpa_wait2() {
    asm volatile("cp.async.wait_group 2;");
}

__global__ __launch_bounds__(NTH) void psi11t_kernel(
    const float* __restrict__ s,
    const float* __restrict__ tt,
    const float* __restrict__ c0,
    float* __restrict__ out)
{
    __shared__ float ring[4][3][512];       // 24576 B: 4-row-slot ring
    __shared__ float bw[2][NTH], bx[2][NTH];

    const int bb = blockIdx.y;
    const int x0 = blockIdx.x * XCHUNK;
    const int t  = threadIdx.x;
    const int tm = (t - 1) & (NTH - 1);
    const int tp = (t + 1) & (NTH - 1);
    const long base = (long)bb * (3L << 18);
    const float* sb = s + base;
    const int yo  = 4 * t;
    const int ym1 = (yo - 1) & MASK;
    const int yp4 = (yo + 4) & MASK;

    const float coeff = 2.0f * tt[0] * c0[0];

    // ---- issue cp.async for rows x0+2, x0+3 first (max overlap) ----
    {
        const int r2 = (x0 + 2) & MASK, r3 = (x0 + 3) & MASK;
        #pragma unroll
        for (int c = 0; c < 3; ++c)
            cpa16(&ring[(x0 + 2) & 3][c][yo], sb + ((long)c << 18) + ((long)r2 << 9) + yo);
        cpa_commit();
        #pragma unroll
        for (int c = 0; c < 3; ++c)
            cpa16(&ring[(x0 + 3) & 3][c][yo], sb + ((long)c << 18) + ((long)r3 << 9) + yo);
        cpa_commit();
    }

    // Persistent state: 3 s-rows, 2 b-rows, boundary scalars.
    float4 sP[3], sC[3], sN[3];
    float4 bP, bC;
    float  sClw[3], sCrx[3], sNlw[3], sNrx[3];
    float  bClw, bCrx;

    // ---------------- Prologue: rows x0-2 .. x0+1 (direct LDG) ----------------
    {
        const int rA = (x0 - 2) & MASK, rP = (x0 - 1) & MASK;
        const int rC = x0, rN = x0 + 1;
        float4 sA[3];
        float plw[3], prx[3];
        #pragma unroll
        for (int c = 0; c < 3; ++c) {
            const float* cp = sb + ((long)c << 18);
            sA[c] = *(const float4*)(cp + ((long)rA << 9) + yo);
            sP[c] = *(const float4*)(cp + ((long)rP << 9) + yo);
            sC[c] = *(const float4*)(cp + ((long)rC << 9) + yo);
            sN[c] = *(const float4*)(cp + ((long)rN << 9) + yo);
            plw[c]  = cp[((long)rP << 9) + ym1];  prx[c]  = cp[((long)rP << 9) + yp4];
            sClw[c] = cp[((long)rC << 9) + ym1];  sCrx[c] = cp[((long)rC << 9) + yp4];
            sNlw[c] = cp[((long)rN << 9) + ym1];  sNrx[c] = cp[((long)rN << 9) + yp4];
        }

        // bP = sP . (sA + sC + ym(sP) + yp(sP))
        bP = make_float4(0.f, 0.f, 0.f, 0.f);
        #pragma unroll
        for (int c = 0; c < 3; ++c)
            bP = fma4(sP[c], sA[c] + sC[c] + ymv(sP[c], plw[c]) + ypv(sP[c], prx[c]), bP);

        // bC = sC . (sP + sN + ym(sC) + yp(sC))
        bC = make_float4(0.f, 0.f, 0.f, 0.f);
        #pragma unroll
        for (int c = 0; c < 3; ++c)
            bC = fma4(sC[c], sP[c] + sN[c] + ymv(sC[c], sClw[c]) + ypv(sC[c], sCrx[c]), bC);

        // exchange bC bounds via buffer 1 (main loop starts on buffer 0)
        bw[1][t] = bC.w; bx[1][t] = bC.x;
        __syncthreads();
        bClw = bw[1][tm]; bCrx = bx[1][tp];
    }

    // ---------------- Main loop: output rows x0 .. x0+XCHUNK-1 ----------------
    #pragma unroll 2
    for (int i = 0; i < XCHUNK; ++i) {
        const int x = x0 + i;
        const int p = i & 1;

        // 1. prefetch row x+4 into slot (x+4)&3 (old content dead by barrier logic)
        {
            const int r4 = (x + 4) & MASK;
            float* dst = &ring[(x + 4) & 3][0][0];
            #pragma unroll
            for (int c = 0; c < 3; ++c)
                cpa16(&ring[(x + 4) & 3][c][yo],
                      sb + ((long)c << 18) + ((long)r4 << 9) + yo);
            cpa_commit();
            (void)dst;
        }

        // 2. wait for row x+2 (committed 2 groups ago), read own vector
        cpa_wait2();
        const int slot2 = (x + 2) & 3;
        float4 sN2[3];
        #pragma unroll
        for (int c = 0; c < 3; ++c)
            sN2[c] = *(const float4*)&ring[slot2][c][yo];

        // 3. bN = sN . (sC + sN2 + ym(sN) + yp(sN))   [b at row x+1]
        float4 bN = make_float4(0.f, 0.f, 0.f, 0.f);
        #pragma unroll
        for (int c = 0; c < 3; ++c)
            bN = fma4(sN[c], sC[c] + sN2[c] + ymv(sN[c], sNlw[c]) + ypv(sN[c], sNrx[c]), bN);

        // 4. publish bN bounds
        bw[p][t] = bN.w; bx[p][t] = bN.x;
        __syncthreads();

        // 5. post-sync reads: bN bounds + row x+2 bounds (neighbor cp.async data)
        const float bNlw = bw[p][tm], bNrx = bx[p][tp];
        float n2lw[3], n2rx[3];
        #pragma unroll
        for (int c = 0; c < 3; ++c) {
            n2lw[c] = ring[slot2][c][ym1];
            n2rx[c] = ring[slot2][c][yp4];
        }

        // 6. F at row x
        const float4 bym = ymv(bC, bClw);
        const float4 byp = ypv(bC, bCrx);
        float4 Fv[3];
        #pragma unroll
        for (int c = 0; c < 3; ++c) {
            const float4 ymc = ymv(sC[c], sClw[c]);
            const float4 ypc = ypv(sC[c], sCrx[c]);
            const float4 Fs  = sP[c] + sN[c] + ymc + ypc;
            const float4 Fbs = fma4(sP[c], bP,
                               fma4(sN[c], bN,
                               fma4(ymc, bym,
                                    make_float4(ypc.x * byp.x, ypc.y * byp.y,
                                                ypc.z * byp.z, ypc.w * byp.w))));
            Fv[c] = fma4(Fs, bC, Fbs);
        }

        float* op = out + base + (((long)x) << 9) + yo;
        __stcs((float4*)(op),              scale4(coeff, crossm(sC[1], Fv[2], sC[2], Fv[1])));
        __stcs((float4*)(op + (1L << 18)), scale4(coeff, crossm(sC[2], Fv[0], sC[0], Fv[2])));
        __stcs((float4*)(op + (2L << 18)), scale4(coeff, crossm(sC[0], Fv[1], sC[1], Fv[0])));

        // 7. rotate pipeline (register renames under unroll 2)
        #pragma unroll
        for (int c = 0; c < 3; ++c) {
            sP[c] = sC[c]; sC[c] = sN[c]; sN[c] = sN2[c];
            sClw[c] = sNlw[c]; sCrx[c] = sNrx[c];
            sNlw[c] = n2lw[c]; sNrx[c] = n2rx[c];
        }
        bP = bC; bC = bN;
        bClw = bNlw; bCrx = bNrx;
    }
}

extern "C" void kernel_launch(void* const* d_in, const int* in_sizes, int n_in,
                              void* d_out, int out_size)
{
    const float* s  = (const float*)d_in[0];
    const float* t  = (const float*)d_in[1];
    const float* c0 = (const float*)d_in[2];
    float* out = (float*)d_out;

    dim3 grid(512 / XCHUNK, 32);   // 32 x-strips * 32 batches = 1024 blocks
    psi11t_kernel<<<grid, NTH>>>(s, t, c0, out);
}

// round 9
// speedup vs baseline: 1.5067x; 1.0370x over previous
#include <cuda_runtime.h>
#include <cstdint>

// Psi11t flow force: F = 2*t*c0 * ( s x (Fs*b + Fbs) )
//   Fs = nbr4(s), b = s.Fs, Fbs = nbr4(s*b). Periodic 512x512, B=32, S=3.
// Register-marching stencil + cp.async smem row-ring (4 slots, distance-2
// prefetch). 128 threads own the full Y=512 ring (float4/thread), march
// XCHUNK=32 x-rows (single resident wave: 512 blocks <= 148 SM x 4 blk).
// s-row boundary scalars read from the smem ring; b bounds via STS/LDS.

#define MASK 511
#define XCHUNK 32
#define NTH 128

__device__ __forceinline__ float4 operator+(float4 a, float4 b) {
    return make_float4(a.x + b.x, a.y + b.y, a.z + b.z, a.w + b.w);
}
__device__ __forceinline__ float4 fma4(float4 a, float4 b, float4 c) {
    return make_float4(fmaf(a.x, b.x, c.x), fmaf(a.y, b.y, c.y),
                       fmaf(a.z, b.z, c.z), fmaf(a.w, b.w, c.w));
}
__device__ __forceinline__ float4 crossm(float4 a, float4 b, float4 c, float4 d) {
    return make_float4(fmaf(a.x, b.x, -(c.x * d.x)), fmaf(a.y, b.y, -(c.y * d.y)),
                       fmaf(a.z, b.z, -(c.z * d.z)), fmaf(a.w, b.w, -(c.w * d.w)));
}
__device__ __forceinline__ float4 ymv(float4 a, float lw) {
    return make_float4(lw, a.x, a.y, a.z);
}
__device__ __forceinline__ float4 ypv(float4 a, float rx) {
    return make_float4(a.y, a.z, a.w, rx);
}
__device__ __forceinline__ float4 scale4(float k, float4 a) {
    return make_float4(k * a.x, k * a.y, k * a.z, k * a.w);
}
__device__ __forceinline__ void cpa16(float* smem_dst, const float* g) {
    uint32_t sa = (uint32_t)__cvta_generic_to_shared(smem_dst);
    asm volatile("cp.async.cg.shared.global [%0], [%1], 16;" :: "r"(sa), "l"(g));
}
__device__ __forceinline__ void cpa_commit() {
    asm volatile("cp.async.commit_group;");
}
__device__ __forceinline__ void cpa_wait2() {
    asm volatile("cp.async.wait_group 2;");
}

__global__ __launch_bounds__(NTH) void psi11t_kernel(
    const float* __restrict__ s,
    const float* __restrict__ tt,
    const float* __restrict__ c0,
    float* __restrict__ out)
{
    __shared__ float ring[4][3][512];       // 24576 B: 4-row-slot ring
    __shared__ float bw[2][NTH], bx[2][NTH];

    const int bb = blockIdx.y;
    const int x0 = blockIdx.x * XCHUNK;
    const int t  = threadIdx.x;
    const int tm = (t - 1) & (NTH - 1);
    const int tp = (t + 1) & (NTH - 1);
    const long base = (long)bb * (3L << 18);
    const float* sb = s + base;
    const int yo  = 4 * t;
    const int ym1 = (yo - 1) & MASK;
    const int yp4 = (yo + 4) & MASK;

    const float coeff = 2.0f * tt[0] * c0[0];

    // ---- issue cp.async for rows x0+2, x0+3 first (max overlap) ----
    {
        const int r2 = (x0 + 2) & MASK, r3 = (x0 + 3) & MASK;
        #pragma unroll
        for (int c = 0; c < 3; ++c)
            cpa16(&ring[(x0 + 2) & 3][c][yo], sb + ((long)c << 18) + ((long)r2 << 9) + yo);
        cpa_commit();
        #pragma unroll
        for (int c = 0; c < 3; ++c)
            cpa16(&ring[(x0 + 3) & 3][c][yo], sb + ((long)c << 18) + ((long)r3 << 9) + yo);
        cpa_commit();
    }

    // Persistent state: 3 s-rows, 2 b-rows, boundary scalars.
    float4 sP[3], sC[3], sN[3];
    float4 bP, bC;
    float  sClw[3], sCrx[3], sNlw[3], sNrx[3];
    float  bClw, bCrx;

    // ---------------- Prologue: rows x0-2 .. x0+1 (direct LDG) ----------------
    {
        const int rA = (x0 - 2) & MASK, rP = (x0 - 1) & MASK;
        const int rC = x0, rN = x0 + 1;
        float4 sA[3];
        float plw[3], prx[3];
        #pragma unroll
        for (int c = 0; c < 3; ++c) {
            const float* cp = sb + ((long)c << 18);
            sA[c] = *(const float4*)(cp + ((long)rA << 9) + yo);
            sP[c] = *(const float4*)(cp + ((long)rP << 9) + yo);
            sC[c] = *(const float4*)(cp + ((long)rC << 9) + yo);
            sN[c] = *(const float4*)(cp + ((long)rN << 9) + yo);
            plw[c]  = cp[((long)rP << 9) + ym1];  prx[c]  = cp[((long)rP << 9) + yp4];
            sClw[c] = cp[((long)rC << 9) + ym1];  sCrx[c] = cp[((long)rC << 9) + yp4];
            sNlw[c] = cp[((long)rN << 9) + ym1];  sNrx[c] = cp[((long)rN << 9) + yp4];
        }

        // bP = sP . (sA + sC + ym(sP) + yp(sP))
        bP = make_float4(0.f, 0.f, 0.f, 0.f);
        #pragma unroll
        for (int c = 0; c < 3; ++c)
            bP = fma4(sP[c], sA[c] + sC[c] + ymv(sP[c], plw[c]) + ypv(sP[c], prx[c]), bP);

        // bC = sC . (sP + sN + ym(sC) + yp(sC))
        bC = make_float4(0.f, 0.f, 0.f, 0.f);
        #pragma unroll
        for (int c = 0; c < 3; ++c)
            bC = fma4(sC[c], sP[c] + sN[c] + ymv(sC[c], sClw[c]) + ypv(sC[c], sCrx[c]), bC);

        // exchange bC bounds via buffer 1 (main loop starts on buffer 0)
        bw[1][t] = bC.w; bx[1][t] = bC.x;
        __syncthreads();
        bClw = bw[1][tm]; bCrx = bx[1][tp];
    }

    // ---------------- Main loop: output rows x0 .. x0+XCHUNK-1 ----------------
    #pragma unroll 2
    for (int i = 0; i < XCHUNK; ++i) {
        const int x = x0 + i;
        const int p = i & 1;

        // 1. prefetch row x+4 into slot (x+4)&3 (old row-x data fully consumed
        //    before the previous iteration's __syncthreads)
        {
            const int r4 = (x + 4) & MASK;
            #pragma unroll
            for (int c = 0; c < 3; ++c)
                cpa16(&ring[(x + 4) & 3][c][yo],
                      sb + ((long)c << 18) + ((long)r4 << 9) + yo);
            cpa_commit();
        }

        // 2. wait for row x+2 (committed 2 groups ago), read own vector
        cpa_wait2();
        const int slot2 = (x + 2) & 3;
        float4 sN2[3];
        #pragma unroll
        for (int c = 0; c < 3; ++c)
            sN2[c] = *(const float4*)&ring[slot2][c][yo];

        // 3. bN = sN . (sC + sN2 + ym(sN) + yp(sN))   [b at row x+1]
        float4 bN = make_float4(0.f, 0.f, 0.f, 0.f);
        #pragma unroll
        for (int c = 0; c < 3; ++c)
            bN = fma4(sN[c], sC[c] + sN2[c] + ymv(sN[c], sNlw[c]) + ypv(sN[c], sNrx[c]), bN);

        // 4. publish bN bounds
        bw[p][t] = bN.w; bx[p][t] = bN.x;
        __syncthreads();

        // 5. post-sync reads: bN bounds + row x+2 bounds (neighbor cp.async data)
        const float bNlw = bw[p][tm], bNrx = bx[p][tp];
        float n2lw[3], n2rx[3];
        #pragma unroll
        for (int c = 0; c < 3; ++c) {
            n2lw[c] = ring[slot2][c][ym1];
            n2rx[c] = ring[slot2][c][yp4];
        }

        // 6. F at row x
        const float4 bym = ymv(bC, bClw);
        const float4 byp = ypv(bC, bCrx);
        float4 Fv[3];
        #pragma unroll
        for (int c = 0; c < 3; ++c) {
            const float4 ymc = ymv(sC[c], sClw[c]);
            const float4 ypc = ypv(sC[c], sCrx[c]);
            const float4 Fs  = sP[c] + sN[c] + ymc + ypc;
            const float4 Fbs = fma4(sP[c], bP,
                               fma4(sN[c], bN,
                               fma4(ymc, bym,
                                    make_float4(ypc.x * byp.x, ypc.y * byp.y,
                                                ypc.z * byp.z, ypc.w * byp.w))));
            Fv[c] = fma4(Fs, bC, Fbs);
        }

        float* op = out + base + (((long)x) << 9) + yo;
        __stcs((float4*)(op),              scale4(coeff, crossm(sC[1], Fv[2], sC[2], Fv[1])));
        __stcs((float4*)(op + (1L << 18)), scale4(coeff, crossm(sC[2], Fv[0], sC[0], Fv[2])));
        __stcs((float4*)(op + (2L << 18)), scale4(coeff, crossm(sC[0], Fv[1], sC[1], Fv[0])));

        // 7. rotate pipeline (register renames under unroll 2)
        #pragma unroll
        for (int c = 0; c < 3; ++c) {
            sP[c] = sC[c]; sC[c] = sN[c]; sN[c] = sN2[c];
            sClw[c] = sNlw[c]; sCrx[c] = sNrx[c];
            sNlw[c] = n2lw[c]; sNrx[c] = n2rx[c];
        }
        bP = bC; bC = bN;
        bClw = bNlw; bCrx = bNrx;
    }
}

extern "C" void kernel_launch(void* const* d_in, const int* in_sizes, int n_in,
                              void* d_out, int out_size)
{
    const float* s  = (const float*)d_in[0];
    const float* t  = (const float*)d_in[1];
    const float* c0 = (const float*)d_in[2];
    float* out = (float*)d_out;

    dim3 grid(512 / XCHUNK, 32);   // 16 x-strips * 32 batches = 512 blocks
    psi11t_kernel<<<grid, NTH>>>(s, t, c0, out);
}